// round 15
// baseline (speedup 1.0000x reference)
#include <cuda_runtime.h>
#include <cuda_fp16.h>
#include <math.h>
#include <stdint.h>

#define BB   8
#define TT   1024
#define DD   1024
#define HH   16
#define EE   64
#define FF   4096
#define BT   (BB*TT)   // 8192

// ---------------- scratch (device globals; no allocs allowed) ----------------
__device__ float  g_xn  [BT*DD];
__device__ float  g_x2  [BT*DD];
__device__ float  g_xn2 [BT*DD];
__device__ __half g_xnh [BT*DD];
__device__ __half g_qkvh[BT*3*DD];
__device__ __half g_atth[BT*DD];
__device__ __half g_xn2h[BT*DD];
__device__ __half g_hh  [BT*FF];
__device__ __half g_wqkvt[3*DD*DD];
__device__ __half g_wpt [DD*DD];
__device__ __half g_w1t [FF*DD];
__device__ __half g_w2t [DD*FF];

// ---------------- asm helpers ----------------
__device__ __forceinline__ void mma_f16(float* d, const unsigned* a, unsigned b0, unsigned b1) {
    asm volatile(
        "mma.sync.aligned.m16n8k16.row.col.f32.f16.f16.f32 "
        "{%0,%1,%2,%3}, {%4,%5,%6,%7}, {%8,%9}, {%0,%1,%2,%3};\n"
        : "+f"(d[0]), "+f"(d[1]), "+f"(d[2]), "+f"(d[3])
        : "r"(a[0]), "r"(a[1]), "r"(a[2]), "r"(a[3]), "r"(b0), "r"(b1));
}
__device__ __forceinline__ void mma_h16(unsigned* d, const unsigned* a, unsigned b0, unsigned b1) {
    asm volatile(
        "mma.sync.aligned.m16n8k16.row.col.f16.f16.f16.f16 "
        "{%0,%1}, {%2,%3,%4,%5}, {%6,%7}, {%0,%1};\n"
        : "+r"(d[0]), "+r"(d[1])
        : "r"(a[0]), "r"(a[1]), "r"(a[2]), "r"(a[3]), "r"(b0), "r"(b1));
}
#define LDSM4(r0,r1,r2,r3,addr) \
    asm volatile("ldmatrix.sync.aligned.m8n8.x4.shared.b16 {%0,%1,%2,%3}, [%4];" \
        : "=r"(r0), "=r"(r1), "=r"(r2), "=r"(r3) : "r"(addr))
#define LDSM4T(r0,r1,r2,r3,addr) \
    asm volatile("ldmatrix.sync.aligned.m8n8.x4.trans.shared.b16 {%0,%1,%2,%3}, [%4];" \
        : "=r"(r0), "=r"(r1), "=r"(r2), "=r"(r3) : "r"(addr))
// streaming copies: .cg = L2-only (operands are read-once; skip L1 fill)
#define CP16(sm, gm) asm volatile("cp.async.cg.shared.global [%0], [%1], 16;\n" :: "r"(sm), "l"(gm))

__device__ __forceinline__ unsigned h2u(__half2 h) { return *reinterpret_cast<unsigned*>(&h); }

// ---------------- weight prep ----------------
__global__ void transpose_cvt(const float* __restrict__ in, __half* __restrict__ out,
                              int K, int N) {
    __shared__ float tile[32][33];
    int n0 = blockIdx.x * 32, k0 = blockIdx.y * 32;
    int tx = threadIdx.x, ty = threadIdx.y;
    #pragma unroll
    for (int i = 0; i < 32; i += 8)
        tile[ty + i][tx] = in[(size_t)(k0 + ty + i) * N + n0 + tx];
    __syncthreads();
    #pragma unroll
    for (int i = 0; i < 32; i += 8)
        out[(size_t)(n0 + ty + i) * K + k0 + tx] = __float2half(tile[tx][ty + i]);
}

__global__ void qkv_w_prep(const float* __restrict__ wq, const float* __restrict__ wk,
                           const float* __restrict__ wv, __half* __restrict__ wt) {
    __shared__ float tile[32][33];
    int slot = blockIdx.z, s = slot >> 4, h = slot & 15;
    const float* w = ((s == 0) ? wq : (s == 1) ? wk : wv) + (size_t)h * DD * EE;
    __half* o = wt + (size_t)(s * DD + h * EE) * DD;
    int e0 = blockIdx.x * 32, k0 = blockIdx.y * 32;
    int tx = threadIdx.x, ty = threadIdx.y;
    #pragma unroll
    for (int i = 0; i < 32; i += 8)
        tile[ty + i][tx] = w[(size_t)(k0 + ty + i) * EE + e0 + tx];
    __syncthreads();
    #pragma unroll
    for (int i = 0; i < 32; i += 8)
        o[(size_t)(e0 + ty + i) * DD + k0 + tx] = __float2half(tile[tx][ty + i]);
}

// ---------------- LayerNorm: warp-per-row ----------------
__global__ void ln_kernel(const float* __restrict__ x, const float* __restrict__ g,
                          const float* __restrict__ b, float* __restrict__ y,
                          __half* __restrict__ yh) {
    int warp = threadIdx.x >> 5, lane = threadIdx.x & 31;
    int row = blockIdx.x * 8 + warp;
    const float4* xr = (const float4*)(x + (size_t)row * DD);

    float4 v[8];
    float s = 0.f, sq = 0.f;
    #pragma unroll
    for (int j = 0; j < 8; j++) {
        v[j] = xr[lane + 32 * j];
        s  += v[j].x + v[j].y + v[j].z + v[j].w;
        sq += v[j].x*v[j].x + v[j].y*v[j].y + v[j].z*v[j].z + v[j].w*v[j].w;
    }
    #pragma unroll
    for (int m = 16; m >= 1; m >>= 1) {
        s  += __shfl_xor_sync(0xffffffffu, s,  m);
        sq += __shfl_xor_sync(0xffffffffu, sq, m);
    }
    float mu   = s * (1.0f / DD);
    float var  = sq * (1.0f / DD) - mu * mu;
    float rstd = rsqrtf(var + 1e-5f);

    float4*  yr  = (float4*)(y + (size_t)row * DD);
    __half2* yh2 = (__half2*)(yh + (size_t)row * DD);
    #pragma unroll
    for (int j = 0; j < 8; j++) {
        int idx = lane + 32 * j;
        float4 gg = ((const float4*)g)[idx];
        float4 bv = ((const float4*)b)[idx];
        float4 o;
        o.x = (v[j].x - mu) * rstd * gg.x + bv.x;
        o.y = (v[j].y - mu) * rstd * gg.y + bv.y;
        o.z = (v[j].z - mu) * rstd * gg.z + bv.z;
        o.w = (v[j].w - mu) * rstd * gg.w + bv.w;
        yr[idx] = o;
        yh2[idx * 2]     = __floats2half2_rn(o.x, o.y);
        yh2[idx * 2 + 1] = __floats2half2_rn(o.z, o.w);
    }
}

// ---------------- f16 GEMM 128x128: multistage KB=64 ----------
#define KB2  64
#define PH   72
#define STG  (128*PH)
#define NSTG 3
#define GEMM_SMEM (NSTG * 2 * STG * 2)   // 110592 B

__global__ __launch_bounds__(256) void hgemm(const __half* __restrict__ A,
        const __half* __restrict__ Bt, float* __restrict__ Cf,
        __half* __restrict__ Ch, int M, int N, int K,
        const float* __restrict__ bias, const float* __restrict__ resid, int relu) {
    extern __shared__ __half sh[];
    __half* As = sh;
    __half* Bs = sh + NSTG * STG;

    int tid = threadIdx.x, warp = tid >> 5, lane = tid & 31;
    int wm = warp >> 1, wn = warp & 1;
    int m0 = wm * 32, n0 = wn * 64;
    int rowBase = blockIdx.y * 128, colBase = blockIdx.x * 128;

    int lr = tid >> 1, lcb = (tid & 1) * 32;
    const __half* Ag = A  + (size_t)(rowBase + lr) * K + lcb;
    const __half* Bg = Bt + (size_t)(colBase + lr) * K + lcb;
    uint32_t sA = (uint32_t)__cvta_generic_to_shared(As);
    uint32_t sB = (uint32_t)__cvta_generic_to_shared(Bs);
    uint32_t cpOff = (lr * PH + lcb) * 2;

    #define HG_LOAD(k0, st) do { \
        uint32_t aS = sA + (st) * STG * 2 + cpOff; \
        uint32_t bS = sB + (st) * STG * 2 + cpOff; \
        const __half* ag = Ag + (k0); \
        const __half* bg = Bg + (k0); \
        _Pragma("unroll") \
        for (int j = 0; j < 4; j++) { \
            CP16(aS + j * 16, ag + j * 8); \
            CP16(bS + j * 16, bg + j * 8); \
        } \
    } while (0)

    float acc[2][8][4];
    #pragma unroll
    for (int mi = 0; mi < 2; mi++)
        #pragma unroll
        for (int nj = 0; nj < 8; nj++)
            #pragma unroll
            for (int t = 0; t < 4; t++) acc[mi][nj][t] = 0.f;

    int nk = K / KB2;

    HG_LOAD(0, 0);
    asm volatile("cp.async.commit_group;\n");
    HG_LOAD(KB2, 1);
    asm volatile("cp.async.commit_group;\n");

    uint32_t aF = ((m0 + (lane & 15)) * PH + (lane >> 4) * 8) * 2;
    uint32_t bF = ((n0 + (lane & 7) + ((lane >> 4) & 1) * 8) * PH + ((lane >> 3) & 1) * 8) * 2;

    for (int i = 0; i < nk; i++) {
        asm volatile("cp.async.wait_group 1;\n");
        __syncthreads();

        int ps = i + 2;
        if (ps < nk) HG_LOAD(ps * KB2, ps % NSTG);
        asm volatile("cp.async.commit_group;\n");

        int st = i % NSTG;
        uint32_t aBase = sA + st * STG * 2 + aF;
        uint32_t bBase = sB + st * STG * 2 + bF;

        unsigned hacc[2][8][2];
        #pragma unroll
        for (int mi = 0; mi < 2; mi++)
            #pragma unroll
            for (int nj = 0; nj < 8; nj++) { hacc[mi][nj][0] = 0u; hacc[mi][nj][1] = 0u; }

        #pragma unroll
        for (int kk = 0; kk < 4; kk++) {
            unsigned af[2][4];
            LDSM4(af[0][0], af[0][1], af[0][2], af[0][3], aBase + kk * 32);
            LDSM4(af[1][0], af[1][1], af[1][2], af[1][3], aBase + kk * 32 + 16 * PH * 2);
            unsigned bf[8][2];
            #pragma unroll
            for (int j2 = 0; j2 < 4; j2++) {
                unsigned r0, r1, r2, r3;
                LDSM4(r0, r1, r2, r3, bBase + kk * 32 + j2 * (16 * PH * 2));
                bf[2*j2][0] = r0; bf[2*j2][1] = r1;
                bf[2*j2+1][0] = r2; bf[2*j2+1][1] = r3;
            }
            #pragma unroll
            for (int mi = 0; mi < 2; mi++)
                #pragma unroll
                for (int nj = 0; nj < 8; nj++)
                    mma_h16(hacc[mi][nj], af[mi], bf[nj][0], bf[nj][1]);
        }

        #pragma unroll
        for (int mi = 0; mi < 2; mi++)
            #pragma unroll
            for (int nj = 0; nj < 8; nj++) {
                float2 lo = __half22float2(*reinterpret_cast<__half2*>(&hacc[mi][nj][0]));
                float2 hi = __half22float2(*reinterpret_cast<__half2*>(&hacc[mi][nj][1]));
                acc[mi][nj][0] += lo.x; acc[mi][nj][1] += lo.y;
                acc[mi][nj][2] += hi.x; acc[mi][nj][3] += hi.y;
            }
    }

    #pragma unroll
    for (int mi = 0; mi < 2; mi++) {
        int r = rowBase + m0 + mi * 16 + (lane >> 2);
        #pragma unroll
        for (int nj = 0; nj < 8; nj++) {
            int c = colBase + n0 + nj * 8 + 2 * (lane & 3);
            float v0 = acc[mi][nj][0], v1 = acc[mi][nj][1];
            float v2 = acc[mi][nj][2], v3 = acc[mi][nj][3];
            if (bias)  { v0 += bias[c]; v1 += bias[c+1]; v2 += bias[c]; v3 += bias[c+1]; }
            if (relu)  { v0 = fmaxf(v0, 0.f); v1 = fmaxf(v1, 0.f);
                         v2 = fmaxf(v2, 0.f); v3 = fmaxf(v3, 0.f); }
            if (resid) {
                const float* rr0 = resid + (size_t)r * N + c;
                const float* rr1 = resid + (size_t)(r + 8) * N + c;
                v0 += rr0[0]; v1 += rr0[1]; v2 += rr1[0]; v3 += rr1[1];
            }
            if (Cf) {
                *(float2*)&Cf[(size_t)r * N + c]       = make_float2(v0, v1);
                *(float2*)&Cf[(size_t)(r + 8) * N + c] = make_float2(v2, v3);
            }
            if (Ch) {
                *(__half2*)&Ch[(size_t)r * N + c]       = __floats2half2_rn(v0, v1);
                *(__half2*)&Ch[(size_t)(r + 8) * N + c] = __floats2half2_rn(v2, v3);
            }
        }
    }
}

// ---------------- f16 flash attention ----------------
#define QP 72
__global__ __launch_bounds__(256) void flash_h(const __half* __restrict__ qkv,
                                               __half* __restrict__ attout) {
    extern __shared__ __half fsh[];
    __half* Qs = fsh;
    __half* Ks = fsh + 128 * QP;
    __half* Vs = Ks + 2 * 64 * QP;

    int tid = threadIdx.x, warp = tid >> 5, lane = tid & 31;
    int qt = gridDim.x - 1 - blockIdx.x;
    int bh = blockIdx.y;
    int b = bh >> 4, h = bh & 15;
    const __half* Qg = qkv + (size_t)b * TT * (3 * DD) + h * EE;
    const __half* Kg = Qg + DD;
    const __half* Vg = Qg + 2 * DD;

    uint32_t sQ = (uint32_t)__cvta_generic_to_shared(Qs);
    uint32_t sK = (uint32_t)__cvta_generic_to_shared(Ks);
    uint32_t sV = (uint32_t)__cvta_generic_to_shared(Vs);

    for (int i = tid; i < 1024; i += 256) {
        int r = i >> 3, c = (i & 7) * 8;
        CP16(sQ + (r * QP + c) * 2, Qg + (size_t)(qt * 128 + r) * (3 * DD) + c);
    }
    asm volatile("cp.async.commit_group;\n");
    for (int i = tid; i < 512; i += 256) {
        int r = i >> 3, c = (i & 7) * 8;
        CP16(sK + (r * QP + c) * 2, Kg + (size_t)r * (3 * DD) + c);
        CP16(sV + (r * QP + c) * 2, Vg + (size_t)r * (3 * DD) + c);
    }
    asm volatile("cp.async.commit_group;\n");
    asm volatile("cp.async.wait_group 1;\n");
    __syncthreads();   // Q staged by other threads

    unsigned qf[4][4];
    {
        uint32_t qb = sQ + (((warp * 16 + (lane & 15)) * QP + (lane >> 4) * 8)) * 2;
        #pragma unroll
        for (int kk = 0; kk < 4; kk++)
            LDSM4(qf[kk][0], qf[kk][1], qf[kk][2], qf[kk][3], qb + kk * 32);
    }

    float m0r = -1e30f, m1r = -1e30f, l0 = 0.f, l1 = 0.f;
    float o[8][4];
    #pragma unroll
    for (int nj = 0; nj < 8; nj++)
        #pragma unroll
        for (int t = 0; t < 4; t++) o[nj][t] = 0.f;

    int grow0 = qt * 128 + warp * 16 + (lane >> 2);
    const float scale = 0.125f;
    int nkt = 2 * qt + 2;

    uint32_t kF = (((lane & 7) + ((lane >> 4) & 1) * 8) * QP + ((lane >> 3) & 1) * 8) * 2;
    uint32_t vF = ((((lane & 7) + ((lane >> 3) & 1) * 8)) * QP + (lane >> 4) * 8) * 2;

    for (int kt = 0; kt < nkt; kt++) {
        asm volatile("cp.async.wait_group 0;\n");
        __syncthreads();

        if (kt + 1 < nkt) {
            int st = (kt + 1) & 1;
            for (int i = tid; i < 512; i += 256) {
                int r = i >> 3, c = (i & 7) * 8;
                CP16(sK + (st * 64 * QP + r * QP + c) * 2,
                     Kg + (size_t)((kt + 1) * 64 + r) * (3 * DD) + c);
                CP16(sV + (st * 64 * QP + r * QP + c) * 2,
                     Vg + (size_t)((kt + 1) * 64 + r) * (3 * DD) + c);
            }
            asm volatile("cp.async.commit_group;\n");
        }

        uint32_t kBase = sK + (kt & 1) * 64 * QP * 2 + kF;
        uint32_t vBase = sV + (kt & 1) * 64 * QP * 2 + vF;

        float s[8][4];
        #pragma unroll
        for (int nj = 0; nj < 8; nj++)
            #pragma unroll
            for (int t = 0; t < 4; t++) s[nj][t] = 0.f;

        #pragma unroll
        for (int kk = 0; kk < 4; kk++) {
            unsigned bf[8][2];
            #pragma unroll
            for (int j2 = 0; j2 < 4; j2++) {
                unsigned r0, r1, r2, r3;
                LDSM4(r0, r1, r2, r3, kBase + kk * 32 + j2 * (16 * QP * 2));
                bf[2*j2][0] = r0; bf[2*j2][1] = r1;
                bf[2*j2+1][0] = r2; bf[2*j2+1][1] = r3;
            }
            #pragma unroll
            for (int nj = 0; nj < 8; nj++)
                mma_f16(s[nj], qf[kk], bf[nj][0], bf[nj][1]);
        }

        bool diag = (kt >= 2 * qt);
        #pragma unroll
        for (int nj = 0; nj < 8; nj++) {
            s[nj][0] *= scale; s[nj][1] *= scale;
            s[nj][2] *= scale; s[nj][3] *= scale;
            if (diag) {
                int gc = kt * 64 + nj * 8 + 2 * (lane & 3);
                if (gc     > grow0)     s[nj][0] = -1e30f;
                if (gc + 1 > grow0)     s[nj][1] = -1e30f;
                if (gc     > grow0 + 8) s[nj][2] = -1e30f;
                if (gc + 1 > grow0 + 8) s[nj][3] = -1e30f;
            }
        }

        float mx0 = -1e30f, mx1 = -1e30f;
        #pragma unroll
        for (int nj = 0; nj < 8; nj++) {
            mx0 = fmaxf(mx0, fmaxf(s[nj][0], s[nj][1]));
            mx1 = fmaxf(mx1, fmaxf(s[nj][2], s[nj][3]));
        }
        mx0 = fmaxf(mx0, __shfl_xor_sync(0xffffffffu, mx0, 1));
        mx0 = fmaxf(mx0, __shfl_xor_sync(0xffffffffu, mx0, 2));
        mx1 = fmaxf(mx1, __shfl_xor_sync(0xffffffffu, mx1, 1));
        mx1 = fmaxf(mx1, __shfl_xor_sync(0xffffffffu, mx1, 2));
        float mn0 = fmaxf(m0r, mx0), mn1 = fmaxf(m1r, mx1);
        float f0 = __expf(m0r - mn0), f1 = __expf(m1r - mn1);
        m0r = mn0; m1r = mn1;
        float rs0 = 0.f, rs1 = 0.f;
        #pragma unroll
        for (int nj = 0; nj < 8; nj++) {
            s[nj][0] = __expf(s[nj][0] - mn0); rs0 += s[nj][0];
            s[nj][1] = __expf(s[nj][1] - mn0); rs0 += s[nj][1];
            s[nj][2] = __expf(s[nj][2] - mn1); rs1 += s[nj][2];
            s[nj][3] = __expf(s[nj][3] - mn1); rs1 += s[nj][3];
        }
        rs0 += __shfl_xor_sync(0xffffffffu, rs0, 1);
        rs0 += __shfl_xor_sync(0xffffffffu, rs0, 2);
        rs1 += __shfl_xor_sync(0xffffffffu, rs1, 1);
        rs1 += __shfl_xor_sync(0xffffffffu, rs1, 2);
        l0 = l0 * f0 + rs0;
        l1 = l1 * f1 + rs1;
        #pragma unroll
        for (int nj = 0; nj < 8; nj++) {
            o[nj][0] *= f0; o[nj][1] *= f0;
            o[nj][2] *= f1; o[nj][3] *= f1;
        }

        #pragma unroll
        for (int kb = 0; kb < 4; kb++) {
            unsigned ph[4];
            #pragma unroll
            for (int q = 0; q < 2; q++) {
                int blk = 2 * kb + q;
                ph[2*q]   = h2u(__floats2half2_rn(s[blk][0], s[blk][1]));
                ph[2*q+1] = h2u(__floats2half2_rn(s[blk][2], s[blk][3]));
            }
            #pragma unroll
            for (int j2 = 0; j2 < 4; j2++) {
                unsigned b0, b1, b2, b3;
                LDSM4T(b0, b1, b2, b3, vBase + kb * (16 * QP * 2) + j2 * 32);
                mma_f16(o[2*j2],   ph, b0, b1);
                mma_f16(o[2*j2+1], ph, b2, b3);
            }
        }
    }

    float inv0 = 1.f / l0, inv1 = 1.f / l1;
    size_t row0 = (size_t)b * TT + qt * 128 + warp * 16 + (lane >> 2);
    #pragma unroll
    for (int nj = 0; nj < 8; nj++) {
        int col = h * EE + nj * 8 + 2 * (lane & 3);
        *(__half2*)&attout[row0 * DD + col] =
            __floats2half2_rn(o[nj][0] * inv0, o[nj][1] * inv0);
        *(__half2*)&attout[(row0 + 8) * DD + col] =
            __floats2half2_rn(o[nj][2] * inv1, o[nj][3] * inv1);
    }
}

// ---------------- launch ----------------
extern "C" void kernel_launch(void* const* d_in, const int* in_sizes, int n_in,
                              void* d_out, int out_size) {
    (void)in_sizes; (void)n_in; (void)out_size;
    const float* x      = (const float*)d_in[0];
    const float* wq     = (const float*)d_in[1];
    const float* wk     = (const float*)d_in[2];
    const float* wv     = (const float*)d_in[3];
    const float* w_proj = (const float*)d_in[4];
    const float* b_proj = (const float*)d_in[5];
    const float* w1     = (const float*)d_in[6];
    const float* b1     = (const float*)d_in[7];
    const float* w2     = (const float*)d_in[8];
    const float* b2     = (const float*)d_in[9];
    const float* g1     = (const float*)d_in[10];
    const float* be1    = (const float*)d_in[11];
    const float* g2     = (const float*)d_in[12];
    const float* be2    = (const float*)d_in[13];
    float* out = (float*)d_out;

    float *p_xn, *p_x2, *p_xn2;
    __half *p_xnh, *p_qkvh, *p_atth, *p_xn2h, *p_hh, *p_wqkvt, *p_wpt, *p_w1t, *p_w2t;
    cudaGetSymbolAddress((void**)&p_xn,    g_xn);
    cudaGetSymbolAddress((void**)&p_x2,    g_x2);
    cudaGetSymbolAddress((void**)&p_xn2,   g_xn2);
    cudaGetSymbolAddress((void**)&p_xnh,   g_xnh);
    cudaGetSymbolAddress((void**)&p_qkvh,  g_qkvh);
    cudaGetSymbolAddress((void**)&p_atth,  g_atth);
    cudaGetSymbolAddress((void**)&p_xn2h,  g_xn2h);
    cudaGetSymbolAddress((void**)&p_hh,    g_hh);
    cudaGetSymbolAddress((void**)&p_wqkvt, g_wqkvt);
    cudaGetSymbolAddress((void**)&p_wpt,   g_wpt);
    cudaGetSymbolAddress((void**)&p_w1t,   g_w1t);
    cudaGetSymbolAddress((void**)&p_w2t,   g_w2t);

    static cudaStream_t s1 = nullptr, s2 = nullptr;
    static cudaEvent_t evRoot = nullptr, evQkvW = nullptr, evW = nullptr;
    if (!s1) {
        cudaStreamCreateWithFlags(&s1, cudaStreamNonBlocking);
        cudaStreamCreateWithFlags(&s2, cudaStreamNonBlocking);
        cudaEventCreateWithFlags(&evRoot, cudaEventDisableTiming);
        cudaEventCreateWithFlags(&evQkvW, cudaEventDisableTiming);
        cudaEventCreateWithFlags(&evW,    cudaEventDisableTiming);
    }

    const int FLASH_SMEM = (128 + 4 * 64) * QP * 2;
    cudaFuncSetAttribute(hgemm,   cudaFuncAttributeMaxDynamicSharedMemorySize, GEMM_SMEM);
    cudaFuncSetAttribute(flash_h, cudaFuncAttributeMaxDynamicSharedMemorySize, FLASH_SMEM);

    cudaEventRecord(evRoot, 0);
    cudaStreamWaitEvent(s1, evRoot, 0);
    cudaStreamWaitEvent(s2, evRoot, 0);

    qkv_w_prep<<<dim3(2, 32, 48), dim3(32, 8), 0, s1>>>(wq, wk, wv, p_wqkvt);
    cudaEventRecord(evQkvW, s1);

    transpose_cvt<<<dim3(32, 32),  dim3(32, 8), 0, s2>>>(w_proj, p_wpt, DD, DD);
    transpose_cvt<<<dim3(128, 32), dim3(32, 8), 0, s2>>>(w1, p_w1t, DD, FF);
    transpose_cvt<<<dim3(32, 128), dim3(32, 8), 0, s2>>>(w2, p_w2t, FF, DD);
    cudaEventRecord(evW, s2);

    // 1. LN1
    ln_kernel<<<BT / 8, 256>>>(x, g1, be1, p_xn, p_xnh);

    cudaStreamWaitEvent(0, evQkvW, 0);
    // 2. fused QKV projection -> f16
    hgemm<<<dim3(24, 64), 256, GEMM_SMEM>>>(p_xnh, p_wqkvt, nullptr, p_qkvh,
                                            BT, 3 * DD, DD, nullptr, nullptr, 0);

    // 3. causal attention -> f16
    flash_h<<<dim3(TT / 128, BB * HH), 256, FLASH_SMEM>>>(p_qkvh, p_atth);

    cudaStreamWaitEvent(0, evW, 0);
    // 4. output projection + bias + residual(xn exact) -> f32
    hgemm<<<dim3(8, 64), 256, GEMM_SMEM>>>(p_atth, p_wpt, p_x2, nullptr,
                                           BT, DD, DD, b_proj, p_xn, 0);

    // 5. LN2
    ln_kernel<<<BT / 8, 256>>>(p_x2, g2, be2, p_xn2, p_xn2h);

    // 6. FFN1 (bias + ReLU) -> f16
    hgemm<<<dim3(32, 64), 256, GEMM_SMEM>>>(p_xn2h, p_w1t, nullptr, p_hh,
                                            BT, FF, DD, b1, nullptr, 1);

    // 7. FFN2 + bias + residual(xn2 exact) -> out f32
    hgemm<<<dim3(8, 64), 256, GEMM_SMEM>>>(p_hh, p_w2t, out, nullptr,
                                           BT, DD, FF, b2, p_xn2, 0);
}

// round 16
// speedup vs baseline: 1.1268x; 1.1268x over previous
#include <cuda_runtime.h>
#include <cuda_fp16.h>
#include <math.h>
#include <stdint.h>

#define BB   8
#define TT   1024
#define DD   1024
#define HH   16
#define EE   64
#define FF   4096
#define BT   (BB*TT)   // 8192

// ---------------- scratch (device globals; no allocs allowed) ----------------
__device__ float  g_xn  [BT*DD];
__device__ float  g_x2  [BT*DD];
__device__ float  g_xn2 [BT*DD];
__device__ __half g_xnh [BT*DD];
__device__ __half g_qkvh[BT*3*DD];
__device__ __half g_atth[BT*DD];
__device__ __half g_xn2h[BT*DD];
__device__ __half g_hh  [BT*FF];
__device__ __half g_wqkvt[3*DD*DD];
__device__ __half g_wpt [DD*DD];
__device__ __half g_w1t [FF*DD];
__device__ __half g_w2t [DD*FF];

// ---------------- asm helpers ----------------
__device__ __forceinline__ void mma_f16(float* d, const unsigned* a, unsigned b0, unsigned b1) {
    asm volatile(
        "mma.sync.aligned.m16n8k16.row.col.f32.f16.f16.f32 "
        "{%0,%1,%2,%3}, {%4,%5,%6,%7}, {%8,%9}, {%0,%1,%2,%3};\n"
        : "+f"(d[0]), "+f"(d[1]), "+f"(d[2]), "+f"(d[3])
        : "r"(a[0]), "r"(a[1]), "r"(a[2]), "r"(a[3]), "r"(b0), "r"(b1));
}
__device__ __forceinline__ void mma_h16(unsigned* d, const unsigned* a, unsigned b0, unsigned b1) {
    asm volatile(
        "mma.sync.aligned.m16n8k16.row.col.f16.f16.f16.f16 "
        "{%0,%1}, {%2,%3,%4,%5}, {%6,%7}, {%0,%1};\n"
        : "+r"(d[0]), "+r"(d[1])
        : "r"(a[0]), "r"(a[1]), "r"(a[2]), "r"(a[3]), "r"(b0), "r"(b1));
}
#define LDSM4(r0,r1,r2,r3,addr) \
    asm volatile("ldmatrix.sync.aligned.m8n8.x4.shared.b16 {%0,%1,%2,%3}, [%4];" \
        : "=r"(r0), "=r"(r1), "=r"(r2), "=r"(r3) : "r"(addr))
#define LDSM4T(r0,r1,r2,r3,addr) \
    asm volatile("ldmatrix.sync.aligned.m8n8.x4.trans.shared.b16 {%0,%1,%2,%3}, [%4];" \
        : "=r"(r0), "=r"(r1), "=r"(r2), "=r"(r3) : "r"(addr))
// .ca: keep L1 fill — co-resident CTAs share A/B tile lines in L1 (R15 lesson)
#define CP16(sm, gm) asm volatile("cp.async.ca.shared.global [%0], [%1], 16;\n" :: "r"(sm), "l"(gm))

__device__ __forceinline__ unsigned h2u(__half2 h) { return *reinterpret_cast<unsigned*>(&h); }

// ---------------- weight prep ----------------
__global__ void transpose_cvt(const float* __restrict__ in, __half* __restrict__ out,
                              int K, int N) {
    __shared__ float tile[32][33];
    int n0 = blockIdx.x * 32, k0 = blockIdx.y * 32;
    int tx = threadIdx.x, ty = threadIdx.y;
    #pragma unroll
    for (int i = 0; i < 32; i += 8)
        tile[ty + i][tx] = in[(size_t)(k0 + ty + i) * N + n0 + tx];
    __syncthreads();
    #pragma unroll
    for (int i = 0; i < 32; i += 8)
        out[(size_t)(n0 + ty + i) * K + k0 + tx] = __float2half(tile[tx][ty + i]);
}

__global__ void qkv_w_prep(const float* __restrict__ wq, const float* __restrict__ wk,
                           const float* __restrict__ wv, __half* __restrict__ wt) {
    __shared__ float tile[32][33];
    int slot = blockIdx.z, s = slot >> 4, h = slot & 15;
    const float* w = ((s == 0) ? wq : (s == 1) ? wk : wv) + (size_t)h * DD * EE;
    __half* o = wt + (size_t)(s * DD + h * EE) * DD;
    int e0 = blockIdx.x * 32, k0 = blockIdx.y * 32;
    int tx = threadIdx.x, ty = threadIdx.y;
    #pragma unroll
    for (int i = 0; i < 32; i += 8)
        tile[ty + i][tx] = w[(size_t)(k0 + ty + i) * EE + e0 + tx];
    __syncthreads();
    #pragma unroll
    for (int i = 0; i < 32; i += 8)
        o[(size_t)(e0 + ty + i) * DD + k0 + tx] = __float2half(tile[tx][ty + i]);
}

// ---------------- LayerNorm: warp-per-row ----------------
__global__ void ln_kernel(const float* __restrict__ x, const float* __restrict__ g,
                          const float* __restrict__ b, float* __restrict__ y,
                          __half* __restrict__ yh) {
    int warp = threadIdx.x >> 5, lane = threadIdx.x & 31;
    int row = blockIdx.x * 8 + warp;
    const float4* xr = (const float4*)(x + (size_t)row * DD);

    float4 v[8];
    float s = 0.f, sq = 0.f;
    #pragma unroll
    for (int j = 0; j < 8; j++) {
        v[j] = xr[lane + 32 * j];
        s  += v[j].x + v[j].y + v[j].z + v[j].w;
        sq += v[j].x*v[j].x + v[j].y*v[j].y + v[j].z*v[j].z + v[j].w*v[j].w;
    }
    #pragma unroll
    for (int m = 16; m >= 1; m >>= 1) {
        s  += __shfl_xor_sync(0xffffffffu, s,  m);
        sq += __shfl_xor_sync(0xffffffffu, sq, m);
    }
    float mu   = s * (1.0f / DD);
    float var  = sq * (1.0f / DD) - mu * mu;
    float rstd = rsqrtf(var + 1e-5f);

    float4*  yr  = (float4*)(y + (size_t)row * DD);
    __half2* yh2 = (__half2*)(yh + (size_t)row * DD);
    #pragma unroll
    for (int j = 0; j < 8; j++) {
        int idx = lane + 32 * j;
        float4 gg = ((const float4*)g)[idx];
        float4 bv = ((const float4*)b)[idx];
        float4 o;
        o.x = (v[j].x - mu) * rstd * gg.x + bv.x;
        o.y = (v[j].y - mu) * rstd * gg.y + bv.y;
        o.z = (v[j].z - mu) * rstd * gg.z + bv.z;
        o.w = (v[j].w - mu) * rstd * gg.w + bv.w;
        yr[idx] = o;
        yh2[idx * 2]     = __floats2half2_rn(o.x, o.y);
        yh2[idx * 2 + 1] = __floats2half2_rn(o.z, o.w);
    }
}

// ---------------- f16 GEMM 128x128: multistage KB=64 ----------
#define KB2  64
#define PH   72
#define STG  (128*PH)
#define NSTG 3
#define GEMM_SMEM (NSTG * 2 * STG * 2)   // 110592 B

__global__ __launch_bounds__(256) void hgemm(const __half* __restrict__ A,
        const __half* __restrict__ Bt, float* __restrict__ Cf,
        __half* __restrict__ Ch, int M, int N, int K,
        const float* __restrict__ bias, const float* __restrict__ resid, int relu) {
    extern __shared__ __half sh[];
    __half* As = sh;
    __half* Bs = sh + NSTG * STG;

    int tid = threadIdx.x, warp = tid >> 5, lane = tid & 31;
    int wm = warp >> 1, wn = warp & 1;
    int m0 = wm * 32, n0 = wn * 64;
    int rowBase = blockIdx.y * 128, colBase = blockIdx.x * 128;

    int lr = tid >> 1, lcb = (tid & 1) * 32;
    const __half* Ag = A  + (size_t)(rowBase + lr) * K + lcb;
    const __half* Bg = Bt + (size_t)(colBase + lr) * K + lcb;
    uint32_t sA = (uint32_t)__cvta_generic_to_shared(As);
    uint32_t sB = (uint32_t)__cvta_generic_to_shared(Bs);
    uint32_t cpOff = (lr * PH + lcb) * 2;

    #define HG_LOAD(k0, st) do { \
        uint32_t aS = sA + (st) * STG * 2 + cpOff; \
        uint32_t bS = sB + (st) * STG * 2 + cpOff; \
        const __half* ag = Ag + (k0); \
        const __half* bg = Bg + (k0); \
        _Pragma("unroll") \
        for (int j = 0; j < 4; j++) { \
            CP16(aS + j * 16, ag + j * 8); \
            CP16(bS + j * 16, bg + j * 8); \
        } \
    } while (0)

    float acc[2][8][4];
    #pragma unroll
    for (int mi = 0; mi < 2; mi++)
        #pragma unroll
        for (int nj = 0; nj < 8; nj++)
            #pragma unroll
            for (int t = 0; t < 4; t++) acc[mi][nj][t] = 0.f;

    int nk = K / KB2;

    HG_LOAD(0, 0);
    asm volatile("cp.async.commit_group;\n");
    HG_LOAD(KB2, 1);
    asm volatile("cp.async.commit_group;\n");

    uint32_t aF = ((m0 + (lane & 15)) * PH + (lane >> 4) * 8) * 2;
    uint32_t bF = ((n0 + (lane & 7) + ((lane >> 4) & 1) * 8) * PH + ((lane >> 3) & 1) * 8) * 2;

    for (int i = 0; i < nk; i++) {
        asm volatile("cp.async.wait_group 1;\n");
        __syncthreads();

        int ps = i + 2;
        if (ps < nk) HG_LOAD(ps * KB2, ps % NSTG);
        asm volatile("cp.async.commit_group;\n");

        int st = i % NSTG;
        uint32_t aBase = sA + st * STG * 2 + aF;
        uint32_t bBase = sB + st * STG * 2 + bF;

        unsigned hacc[2][8][2];
        #pragma unroll
        for (int mi = 0; mi < 2; mi++)
            #pragma unroll
            for (int nj = 0; nj < 8; nj++) { hacc[mi][nj][0] = 0u; hacc[mi][nj][1] = 0u; }

        #pragma unroll
        for (int kk = 0; kk < 4; kk++) {
            unsigned af[2][4];
            LDSM4(af[0][0], af[0][1], af[0][2], af[0][3], aBase + kk * 32);
            LDSM4(af[1][0], af[1][1], af[1][2], af[1][3], aBase + kk * 32 + 16 * PH * 2);
            unsigned bf[8][2];
            #pragma unroll
            for (int j2 = 0; j2 < 4; j2++) {
                unsigned r0, r1, r2, r3;
                LDSM4(r0, r1, r2, r3, bBase + kk * 32 + j2 * (16 * PH * 2));
                bf[2*j2][0] = r0; bf[2*j2][1] = r1;
                bf[2*j2+1][0] = r2; bf[2*j2+1][1] = r3;
            }
            #pragma unroll
            for (int mi = 0; mi < 2; mi++)
                #pragma unroll
                for (int nj = 0; nj < 8; nj++)
                    mma_h16(hacc[mi][nj], af[mi], bf[nj][0], bf[nj][1]);
        }

        #pragma unroll
        for (int mi = 0; mi < 2; mi++)
            #pragma unroll
            for (int nj = 0; nj < 8; nj++) {
                float2 lo = __half22float2(*reinterpret_cast<__half2*>(&hacc[mi][nj][0]));
                float2 hi = __half22float2(*reinterpret_cast<__half2*>(&hacc[mi][nj][1]));
                acc[mi][nj][0] += lo.x; acc[mi][nj][1] += lo.y;
                acc[mi][nj][2] += hi.x; acc[mi][nj][3] += hi.y;
            }
    }

    #pragma unroll
    for (int mi = 0; mi < 2; mi++) {
        int r = rowBase + m0 + mi * 16 + (lane >> 2);
        #pragma unroll
        for (int nj = 0; nj < 8; nj++) {
            int c = colBase + n0 + nj * 8 + 2 * (lane & 3);
            float v0 = acc[mi][nj][0], v1 = acc[mi][nj][1];
            float v2 = acc[mi][nj][2], v3 = acc[mi][nj][3];
            if (bias)  { v0 += bias[c]; v1 += bias[c+1]; v2 += bias[c]; v3 += bias[c+1]; }
            if (relu)  { v0 = fmaxf(v0, 0.f); v1 = fmaxf(v1, 0.f);
                         v2 = fmaxf(v2, 0.f); v3 = fmaxf(v3, 0.f); }
            if (resid) {
                const float* rr0 = resid + (size_t)r * N + c;
                const float* rr1 = resid + (size_t)(r + 8) * N + c;
                v0 += rr0[0]; v1 += rr0[1]; v2 += rr1[0]; v3 += rr1[1];
            }
            if (Cf) {
                *(float2*)&Cf[(size_t)r * N + c]       = make_float2(v0, v1);
                *(float2*)&Cf[(size_t)(r + 8) * N + c] = make_float2(v2, v3);
            }
            if (Ch) {
                *(__half2*)&Ch[(size_t)r * N + c]       = __floats2half2_rn(v0, v1);
                *(__half2*)&Ch[(size_t)(r + 8) * N + c] = __floats2half2_rn(v2, v3);
            }
        }
    }
}

// ---------------- f16 flash attention ----------------
#define QP 72
__global__ __launch_bounds__(256) void flash_h(const __half* __restrict__ qkv,
                                               __half* __restrict__ attout) {
    extern __shared__ __half fsh[];
    __half* Qs = fsh;
    __half* Ks = fsh + 128 * QP;
    __half* Vs = Ks + 2 * 64 * QP;

    int tid = threadIdx.x, warp = tid >> 5, lane = tid & 31;
    int qt = gridDim.x - 1 - blockIdx.x;
    int bh = blockIdx.y;
    int b = bh >> 4, h = bh & 15;
    const __half* Qg = qkv + (size_t)b * TT * (3 * DD) + h * EE;
    const __half* Kg = Qg + DD;
    const __half* Vg = Qg + 2 * DD;

    uint32_t sQ = (uint32_t)__cvta_generic_to_shared(Qs);
    uint32_t sK = (uint32_t)__cvta_generic_to_shared(Ks);
    uint32_t sV = (uint32_t)__cvta_generic_to_shared(Vs);

    for (int i = tid; i < 1024; i += 256) {
        int r = i >> 3, c = (i & 7) * 8;
        CP16(sQ + (r * QP + c) * 2, Qg + (size_t)(qt * 128 + r) * (3 * DD) + c);
    }
    asm volatile("cp.async.commit_group;\n");
    for (int i = tid; i < 512; i += 256) {
        int r = i >> 3, c = (i & 7) * 8;
        CP16(sK + (r * QP + c) * 2, Kg + (size_t)r * (3 * DD) + c);
        CP16(sV + (r * QP + c) * 2, Vg + (size_t)r * (3 * DD) + c);
    }
    asm volatile("cp.async.commit_group;\n");
    asm volatile("cp.async.wait_group 1;\n");
    __syncthreads();   // Q staged by other threads

    unsigned qf[4][4];
    {
        uint32_t qb = sQ + (((warp * 16 + (lane & 15)) * QP + (lane >> 4) * 8)) * 2;
        #pragma unroll
        for (int kk = 0; kk < 4; kk++)
            LDSM4(qf[kk][0], qf[kk][1], qf[kk][2], qf[kk][3], qb + kk * 32);
    }

    float m0r = -1e30f, m1r = -1e30f, l0 = 0.f, l1 = 0.f;
    float o[8][4];
    #pragma unroll
    for (int nj = 0; nj < 8; nj++)
        #pragma unroll
        for (int t = 0; t < 4; t++) o[nj][t] = 0.f;

    int grow0 = qt * 128 + warp * 16 + (lane >> 2);
    const float scale = 0.125f;
    int nkt = 2 * qt + 2;

    uint32_t kF = (((lane & 7) + ((lane >> 4) & 1) * 8) * QP + ((lane >> 3) & 1) * 8) * 2;
    uint32_t vF = ((((lane & 7) + ((lane >> 3) & 1) * 8)) * QP + (lane >> 4) * 8) * 2;

    for (int kt = 0; kt < nkt; kt++) {
        asm volatile("cp.async.wait_group 0;\n");
        __syncthreads();

        if (kt + 1 < nkt) {
            int st = (kt + 1) & 1;
            for (int i = tid; i < 512; i += 256) {
                int r = i >> 3, c = (i & 7) * 8;
                CP16(sK + (st * 64 * QP + r * QP + c) * 2,
                     Kg + (size_t)((kt + 1) * 64 + r) * (3 * DD) + c);
                CP16(sV + (st * 64 * QP + r * QP + c) * 2,
                     Vg + (size_t)((kt + 1) * 64 + r) * (3 * DD) + c);
            }
            asm volatile("cp.async.commit_group;\n");
        }

        uint32_t kBase = sK + (kt & 1) * 64 * QP * 2 + kF;
        uint32_t vBase = sV + (kt & 1) * 64 * QP * 2 + vF;

        float s[8][4];
        #pragma unroll
        for (int nj = 0; nj < 8; nj++)
            #pragma unroll
            for (int t = 0; t < 4; t++) s[nj][t] = 0.f;

        #pragma unroll
        for (int kk = 0; kk < 4; kk++) {
            unsigned bf[8][2];
            #pragma unroll
            for (int j2 = 0; j2 < 4; j2++) {
                unsigned r0, r1, r2, r3;
                LDSM4(r0, r1, r2, r3, kBase + kk * 32 + j2 * (16 * QP * 2));
                bf[2*j2][0] = r0; bf[2*j2][1] = r1;
                bf[2*j2+1][0] = r2; bf[2*j2+1][1] = r3;
            }
            #pragma unroll
            for (int nj = 0; nj < 8; nj++)
                mma_f16(s[nj], qf[kk], bf[nj][0], bf[nj][1]);
        }

        bool diag = (kt >= 2 * qt);
        #pragma unroll
        for (int nj = 0; nj < 8; nj++) {
            s[nj][0] *= scale; s[nj][1] *= scale;
            s[nj][2] *= scale; s[nj][3] *= scale;
            if (diag) {
                int gc = kt * 64 + nj * 8 + 2 * (lane & 3);
                if (gc     > grow0)     s[nj][0] = -1e30f;
                if (gc + 1 > grow0)     s[nj][1] = -1e30f;
                if (gc     > grow0 + 8) s[nj][2] = -1e30f;
                if (gc + 1 > grow0 + 8) s[nj][3] = -1e30f;
            }
        }

        float mx0 = -1e30f, mx1 = -1e30f;
        #pragma unroll
        for (int nj = 0; nj < 8; nj++) {
            mx0 = fmaxf(mx0, fmaxf(s[nj][0], s[nj][1]));
            mx1 = fmaxf(mx1, fmaxf(s[nj][2], s[nj][3]));
        }
        mx0 = fmaxf(mx0, __shfl_xor_sync(0xffffffffu, mx0, 1));
        mx0 = fmaxf(mx0, __shfl_xor_sync(0xffffffffu, mx0, 2));
        mx1 = fmaxf(mx1, __shfl_xor_sync(0xffffffffu, mx1, 1));
        mx1 = fmaxf(mx1, __shfl_xor_sync(0xffffffffu, mx1, 2));
        float mn0 = fmaxf(m0r, mx0), mn1 = fmaxf(m1r, mx1);
        float f0 = __expf(m0r - mn0), f1 = __expf(m1r - mn1);
        m0r = mn0; m1r = mn1;
        float rs0 = 0.f, rs1 = 0.f;
        #pragma unroll
        for (int nj = 0; nj < 8; nj++) {
            s[nj][0] = __expf(s[nj][0] - mn0); rs0 += s[nj][0];
            s[nj][1] = __expf(s[nj][1] - mn0); rs0 += s[nj][1];
            s[nj][2] = __expf(s[nj][2] - mn1); rs1 += s[nj][2];
            s[nj][3] = __expf(s[nj][3] - mn1); rs1 += s[nj][3];
        }
        rs0 += __shfl_xor_sync(0xffffffffu, rs0, 1);
        rs0 += __shfl_xor_sync(0xffffffffu, rs0, 2);
        rs1 += __shfl_xor_sync(0xffffffffu, rs1, 1);
        rs1 += __shfl_xor_sync(0xffffffffu, rs1, 2);
        l0 = l0 * f0 + rs0;
        l1 = l1 * f1 + rs1;
        #pragma unroll
        for (int nj = 0; nj < 8; nj++) {
            o[nj][0] *= f0; o[nj][1] *= f0;
            o[nj][2] *= f1; o[nj][3] *= f1;
        }

        #pragma unroll
        for (int kb = 0; kb < 4; kb++) {
            unsigned ph[4];
            #pragma unroll
            for (int q = 0; q < 2; q++) {
                int blk = 2 * kb + q;
                ph[2*q]   = h2u(__floats2half2_rn(s[blk][0], s[blk][1]));
                ph[2*q+1] = h2u(__floats2half2_rn(s[blk][2], s[blk][3]));
            }
            #pragma unroll
            for (int j2 = 0; j2 < 4; j2++) {
                unsigned b0, b1, b2, b3;
                LDSM4T(b0, b1, b2, b3, vBase + kb * (16 * QP * 2) + j2 * 32);
                mma_f16(o[2*j2],   ph, b0, b1);
                mma_f16(o[2*j2+1], ph, b2, b3);
            }
        }
    }

    float inv0 = 1.f / l0, inv1 = 1.f / l1;
    size_t row0 = (size_t)b * TT + qt * 128 + warp * 16 + (lane >> 2);
    #pragma unroll
    for (int nj = 0; nj < 8; nj++) {
        int col = h * EE + nj * 8 + 2 * (lane & 3);
        *(__half2*)&attout[row0 * DD + col] =
            __floats2half2_rn(o[nj][0] * inv0, o[nj][1] * inv0);
        *(__half2*)&attout[(row0 + 8) * DD + col] =
            __floats2half2_rn(o[nj][2] * inv1, o[nj][3] * inv1);
    }
}

// ---------------- launch ----------------
extern "C" void kernel_launch(void* const* d_in, const int* in_sizes, int n_in,
                              void* d_out, int out_size) {
    (void)in_sizes; (void)n_in; (void)out_size;
    const float* x      = (const float*)d_in[0];
    const float* wq     = (const float*)d_in[1];
    const float* wk     = (const float*)d_in[2];
    const float* wv     = (const float*)d_in[3];
    const float* w_proj = (const float*)d_in[4];
    const float* b_proj = (const float*)d_in[5];
    const float* w1     = (const float*)d_in[6];
    const float* b1     = (const float*)d_in[7];
    const float* w2     = (const float*)d_in[8];
    const float* b2     = (const float*)d_in[9];
    const float* g1     = (const float*)d_in[10];
    const float* be1    = (const float*)d_in[11];
    const float* g2     = (const float*)d_in[12];
    const float* be2    = (const float*)d_in[13];
    float* out = (float*)d_out;

    float *p_xn, *p_x2, *p_xn2;
    __half *p_xnh, *p_qkvh, *p_atth, *p_xn2h, *p_hh, *p_wqkvt, *p_wpt, *p_w1t, *p_w2t;
    cudaGetSymbolAddress((void**)&p_xn,    g_xn);
    cudaGetSymbolAddress((void**)&p_x2,    g_x2);
    cudaGetSymbolAddress((void**)&p_xn2,   g_xn2);
    cudaGetSymbolAddress((void**)&p_xnh,   g_xnh);
    cudaGetSymbolAddress((void**)&p_qkvh,  g_qkvh);
    cudaGetSymbolAddress((void**)&p_atth,  g_atth);
    cudaGetSymbolAddress((void**)&p_xn2h,  g_xn2h);
    cudaGetSymbolAddress((void**)&p_hh,    g_hh);
    cudaGetSymbolAddress((void**)&p_wqkvt, g_wqkvt);
    cudaGetSymbolAddress((void**)&p_wpt,   g_wpt);
    cudaGetSymbolAddress((void**)&p_w1t,   g_w1t);
    cudaGetSymbolAddress((void**)&p_w2t,   g_w2t);

    static cudaStream_t s1 = nullptr, s2 = nullptr;
    static cudaEvent_t evRoot = nullptr, evQkvW = nullptr, evW = nullptr;
    if (!s1) {
        cudaStreamCreateWithFlags(&s1, cudaStreamNonBlocking);
        cudaStreamCreateWithFlags(&s2, cudaStreamNonBlocking);
        cudaEventCreateWithFlags(&evRoot, cudaEventDisableTiming);
        cudaEventCreateWithFlags(&evQkvW, cudaEventDisableTiming);
        cudaEventCreateWithFlags(&evW,    cudaEventDisableTiming);
    }

    const int FLASH_SMEM = (128 + 4 * 64) * QP * 2;
    cudaFuncSetAttribute(hgemm,   cudaFuncAttributeMaxDynamicSharedMemorySize, GEMM_SMEM);
    cudaFuncSetAttribute(flash_h, cudaFuncAttributeMaxDynamicSharedMemorySize, FLASH_SMEM);

    cudaEventRecord(evRoot, 0);
    cudaStreamWaitEvent(s1, evRoot, 0);
    cudaStreamWaitEvent(s2, evRoot, 0);

    qkv_w_prep<<<dim3(2, 32, 48), dim3(32, 8), 0, s1>>>(wq, wk, wv, p_wqkvt);
    cudaEventRecord(evQkvW, s1);

    transpose_cvt<<<dim3(32, 32),  dim3(32, 8), 0, s2>>>(w_proj, p_wpt, DD, DD);
    transpose_cvt<<<dim3(128, 32), dim3(32, 8), 0, s2>>>(w1, p_w1t, DD, FF);
    transpose_cvt<<<dim3(32, 128), dim3(32, 8), 0, s2>>>(w2, p_w2t, FF, DD);
    cudaEventRecord(evW, s2);

    // 1. LN1
    ln_kernel<<<BT / 8, 256>>>(x, g1, be1, p_xn, p_xnh);

    cudaStreamWaitEvent(0, evQkvW, 0);
    // 2. fused QKV projection -> f16
    hgemm<<<dim3(24, 64), 256, GEMM_SMEM>>>(p_xnh, p_wqkvt, nullptr, p_qkvh,
                                            BT, 3 * DD, DD, nullptr, nullptr, 0);

    // 3. causal attention -> f16
    flash_h<<<dim3(TT / 128, BB * HH), 256, FLASH_SMEM>>>(p_qkvh, p_atth);

    cudaStreamWaitEvent(0, evW, 0);
    // 4. output projection + bias + residual(xn exact) -> f32
    hgemm<<<dim3(8, 64), 256, GEMM_SMEM>>>(p_atth, p_wpt, p_x2, nullptr,
                                           BT, DD, DD, b_proj, p_xn, 0);

    // 5. LN2
    ln_kernel<<<BT / 8, 256>>>(p_x2, g2, be2, p_xn2, p_xn2h);

    // 6. FFN1 (bias + ReLU) -> f16
    hgemm<<<dim3(32, 64), 256, GEMM_SMEM>>>(p_xn2h, p_w1t, nullptr, p_hh,
                                            BT, FF, DD, b1, nullptr, 1);

    // 7. FFN2 + bias + residual(xn2 exact) -> out f32
    hgemm<<<dim3(8, 64), 256, GEMM_SMEM>>>(p_hh, p_w2t, out, nullptr,
                                           BT, DD, FF, b2, p_xn2, 0);
}